// round 14
// baseline (speedup 1.0000x reference)
#include <cuda_runtime.h>
#include <cstdint>

// Problem dims
#define NS   512                 // B*S
#define DD   150
#define HH   64
#define GG   192                 // 3H
#define LTT  32
#define LCC  128
#define LSEQ 160                 // LTT + LCC
#define ROWS_T (NS*LTT)          // 16384
#define ROWS_ALL (NS*(LTT+LCC))  // 81920

// Scratch (device globals; no runtime alloc allowed)
__device__ float g_X [ROWS_ALL*DD];   // embed sums (layer0 input)
__device__ float g_xg[ROWS_ALL*GG];   // per-layer input projection, plain [row][gate]
__device__ float g_A [ROWS_ALL*HH];
__device__ float g_B [ROWS_ALL*HH];

// ---------- f32x2 helpers ----------
__device__ __forceinline__ unsigned long long pk2(float a, float b){
    unsigned long long r; asm("mov.b64 %0,{%1,%2};" : "=l"(r) : "f"(a), "f"(b)); return r;
}
__device__ __forceinline__ void fma2(unsigned long long &acc, unsigned long long a, unsigned long long b){
    asm("fma.rn.f32x2 %0, %1, %2, %0;" : "+l"(acc) : "l"(a), "l"(b));
}
__device__ __forceinline__ float upk_sum(unsigned long long a){
    float x, y; asm("mov.b64 {%0,%1}, %2;" : "=f"(x), "=f"(y) : "l"(a)); return x + y;
}
__device__ __forceinline__ float sigmoidf_(float x){
    return __fdividef(1.f, 1.f + __expf(-x));
}
__device__ __forceinline__ float tanhf_(float x){
    float ax = fabsf(x);
    float e  = __expf(-2.f*ax);
    float t  = __fdividef(1.f - e, 1.f + e);
    return (x < 0.f) ? -t : t;
}

// ---------- 1) embedding-bag sums ----------
__global__ void embed_kernel(const int* __restrict__ titles,
                             const int* __restrict__ contents,
                             const float* __restrict__ emb)
{
    int idx = blockIdx.x*blockDim.x + threadIdx.x;
    if (idx >= ROWS_ALL*75) return;          // 75 float2 per row (D=150)
    int row = idx / 75;
    int dp  = idx - row*75;

    const int* ip; int stride;
    if (row < ROWS_T){ int n = row >> 5, t = row & 31;  ip = titles   + (n*6)*32  + t; stride = 32; }
    else             { int r = row - ROWS_T;
                       int n = r >> 7,   t = r & 127;   ip = contents + (n*6)*128 + t; stride = 128; }

    float ax = 0.f, ay = 0.f;
    #pragma unroll
    for (int i = 0; i < 6; i++){
        int ix = ip[i*stride];
        if (ix != 0){
            float2 v = *(const float2*)(emb + (size_t)ix*DD + 2*dp);
            ax += v.x; ay += v.y;
        }
    }
    *(float2*)(g_X + (size_t)row*DD + 2*dp) = make_float2(ax, ay);
}

// ---------- 2a) layer-0 input projection GEMM (K=150), fp32, plain store ----------
__global__ void __launch_bounds__(256, 3) xg_gemm150(const float* __restrict__ W,
                                                     const float* __restrict__ bias)
{
    __shared__ float  sw [30*194];
    __shared__ float2 sxd[64*31];
    int tid = threadIdx.x;
    int tx = tid & 31, ty = tid >> 5;
    int r0 = blockIdx.x * 64;

    unsigned long long acc[8][3];
    #pragma unroll
    for (int r = 0; r < 8; r++)
        #pragma unroll
        for (int c = 0; c < 3; c++) acc[r][c] = 0ull;

    for (int k0 = 0; k0 < 150; k0 += 30){
        for (int i = tid; i < 30*192; i += 256){
            int gg = i/30, kk = i - gg*30;
            sw[kk*194 + gg] = W[gg*150 + k0 + kk];
        }
        for (int i = tid; i < 64*30; i += 256){
            int rr = i/30, kk = i - rr*30;
            float v = g_X[(size_t)(r0+rr)*150 + k0 + kk];
            sxd[rr*31 + kk] = make_float2(v, v);
        }
        __syncthreads();
        #pragma unroll 6
        for (int kk = 0; kk < 30; kk++){
            unsigned long long w2[3];
            #pragma unroll
            for (int c = 0; c < 3; c++)
                w2[c] = *(const unsigned long long*)&sw[kk*194 + tx*6 + 2*c];
            #pragma unroll
            for (int r = 0; r < 8; r++){
                unsigned long long x2 = *(const unsigned long long*)&sxd[(ty*8 + r)*31 + kk];
                #pragma unroll
                for (int c = 0; c < 3; c++) fma2(acc[r][c], w2[c], x2);
            }
        }
        __syncthreads();
    }
    #pragma unroll
    for (int r = 0; r < 8; r++){
        int row = r0 + ty*8 + r;
        #pragma unroll
        for (int c = 0; c < 3; c++){
            float lo, hi;
            asm("mov.b64 {%0,%1}, %2;" : "=f"(lo), "=f"(hi) : "l"(acc[r][c]));
            int g0 = tx*6 + 2*c;
            float2 o; o.x = lo + bias[g0]; o.y = hi + bias[g0+1];
            *(float2*)(g_xg + (size_t)row*GG + g0) = o;
        }
    }
}

// ---------- 2b) K=64 projection GEMM, k-paired f32x2, no duplication ----------
// Tile 64 rows x 96 cols (half of GG). Grid = (ROWS_ALL/64)*2.
// Single smem fill (full K=64), ONE barrier, 16 fully-unrolled 4-k blocks.
#define SWP 68   // padded row stride (floats): 272B, 16B-aligned
__global__ void __launch_bounds__(256, 3) xg_gemm64(const float* __restrict__ X,
                                                    const float* __restrict__ W,
                                                    const float* __restrict__ bias)
{
    __shared__ float sw[96*SWP];
    __shared__ float sx[64*SWP];
    const int tid = threadIdx.x;
    const int tx = tid & 31, ty = tid >> 5;
    const int r0 = (blockIdx.x >> 1) * 64;
    const int c0 = (blockIdx.x & 1) * 96;

    for (int i = tid; i < 96*16; i += 256){
        int g = i >> 4, kq = i & 15;
        float4 v = *(const float4*)(W + (size_t)(c0 + g)*64 + kq*4);
        *(float4*)(sw + g*SWP + kq*4) = v;
    }
    for (int i = tid; i < 64*16; i += 256){
        int r = i >> 4, kq = i & 15;
        float4 v = *(const float4*)(X + (size_t)(r0 + r)*64 + kq*4);
        *(float4*)(sx + r*SWP + kq*4) = v;
    }
    __syncthreads();

    unsigned long long acc[8][3];
    #pragma unroll
    for (int r = 0; r < 8; r++)
        #pragma unroll
        for (int c = 0; c < 3; c++) acc[r][c] = 0ull;

    #pragma unroll
    for (int k4 = 0; k4 < 16; k4++){
        ulonglong2 wv[3];
        #pragma unroll
        for (int c = 0; c < 3; c++)
            wv[c] = *(const ulonglong2*)(sw + (tx + 32*c)*SWP + k4*4);
        #pragma unroll
        for (int r = 0; r < 8; r++){
            ulonglong2 xv = *(const ulonglong2*)(sx + (ty*8 + r)*SWP + k4*4);
            #pragma unroll
            for (int c = 0; c < 3; c++){
                fma2(acc[r][c], wv[c].x, xv.x);
                fma2(acc[r][c], wv[c].y, xv.y);
            }
        }
    }

    #pragma unroll
    for (int r = 0; r < 8; r++){
        int row = r0 + ty*8 + r;
        #pragma unroll
        for (int c = 0; c < 3; c++){
            int col = c0 + tx + 32*c;
            g_xg[(size_t)row*GG + col] = upk_sum(acc[r][c]) + __ldg(bias + col);
        }
    }
}

// ---------- 3) GRU recurrence: 64-thread groups, 2 SEQUENCES per group ----------
// Block 128 = 2 groups of 64 threads; grid 128 (256 groups x 2 seqs = 512 seqs;
// 2 CTAs/SM). Thread k owns gate rows k (r), 64+k (z), 128+k (n) and advances
// BOTH sequences each step — amortizes the fixed per-step latency (LDS, MUFU,
// barrier) over 2x the FMA work with 12 independent accumulator chains.
// One named barrier (id=grp, 64 thr) per step; h double-buffered in shared.
// mode 0: info mid (X layout out), mode 1: info final (concat out), mode 2: comb.
__global__ void __launch_bounds__(128, 2) gru_rec64(
    const float* __restrict__ xg,
    const float* __restrict__ Whh, const float* __restrict__ bhh,
    float* __restrict__ yout, float* __restrict__ hid,
    int mode, int layer)
{
    __shared__ __align__(16) float sh_h[2][2][2][64];   // [grp][buf][seq][elem]

    const int tid = threadIdx.x;
    const int grp = tid >> 6, k = tid & 63;
    const int n0 = (blockIdx.x*2 + grp)*2;    // first seq id of this group (0..510)

    // weight rows r,z,n -> registers (3 x 32 f32x2)
    unsigned long long wr[32], wz[32], wn[32];
    {
        const float2* pr_ = (const float2*)(Whh + (size_t)k*HH);
        const float2* pz_ = (const float2*)(Whh + (size_t)(64 + k)*HH);
        const float2* pn_ = (const float2*)(Whh + (size_t)(128 + k)*HH);
        #pragma unroll
        for (int j = 0; j < 32; j++){
            float2 a = __ldg(pr_ + j); wr[j] = pk2(a.x, a.y);
            float2 b = __ldg(pz_ + j); wz[j] = pk2(b.x, b.y);
            float2 c = __ldg(pn_ + j); wn[j] = pk2(c.x, c.y);
        }
    }
    const float br_ = bhh[k], bz_ = bhh[64 + k], bn_ = bhh[128 + k];

    const int NSEG = (mode == 2) ? 1 : 2;
    float hk[2] = {0.f, 0.f};

    for (int seg = 0; seg < NSEG; seg++){
        int T, ibase[2], ob[2];
        if (mode == 2){
            T = LSEQ;
            #pragma unroll
            for (int s = 0; s < 2; s++){ ibase[s] = (n0+s)*LSEQ; ob[s] = ibase[s]; }
        } else if (seg == 0){   // content
            T = LCC;
            #pragma unroll
            for (int s = 0; s < 2; s++){
                ibase[s] = ROWS_T + (n0+s)*LCC;
                ob[s] = (mode == 1) ? (n0+s)*LSEQ + LTT : ibase[s];
            }
        } else {                // titles
            T = LTT;
            #pragma unroll
            for (int s = 0; s < 2; s++){
                ibase[s] = (n0+s)*LTT;
                ob[s] = (mode == 1) ? (n0+s)*LSEQ : ibase[s];
            }
        }

        hk[0] = hk[1] = 0.f;
        sh_h[grp][0][0][k] = 0.f;
        sh_h[grp][0][1][k] = 0.f;

        float axr[2], axz[2], axn[2];
        #pragma unroll
        for (int s = 0; s < 2; s++){
            int xo = ibase[s]*GG + k;
            axr[s] = __ldg(xg + xo);
            axz[s] = __ldg(xg + xo + 64);
            axn[s] = __ldg(xg + xo + 128);
        }
        asm volatile("bar.sync %0, %1;" :: "r"(grp), "r"(64) : "memory");

        int p = 0;
        for (int t = 0; t < T; t++){
            // prefetch next step's xg (both seqs)
            float nxr[2], nxz[2], nxn[2];
            #pragma unroll
            for (int s = 0; s < 2; s++){
                nxr[s] = nxz[s] = nxn[s] = 0.f;
                if (t+1 < T){
                    int xo = (ibase[s] + t + 1)*GG + k;
                    nxr[s] = __ldg(xg + xo);
                    nxz[s] = __ldg(xg + xo + 64);
                    nxn[s] = __ldg(xg + xo + 128);
                }
            }

            // six matvecs (3 gates x 2 seqs), 2 chains each -> 12 chains
            unsigned long long ar0[2], ar1[2], az0[2], az1[2], an0[2], an1[2];
            #pragma unroll
            for (int s = 0; s < 2; s++){
                ar0[s]=ar1[s]=az0[s]=az1[s]=an0[s]=an1[s]=0ull;
            }
            const ulonglong2* hp0 = (const ulonglong2*)sh_h[grp][p][0];
            const ulonglong2* hp1 = (const ulonglong2*)sh_h[grp][p][1];
            #pragma unroll
            for (int j = 0; j < 16; j++){
                ulonglong2 h4a = hp0[j];
                ulonglong2 h4b = hp1[j];
                fma2(ar0[0], wr[2*j], h4a.x);  fma2(ar1[0], wr[2*j+1], h4a.y);
                fma2(az0[0], wz[2*j], h4a.x);  fma2(az1[0], wz[2*j+1], h4a.y);
                fma2(an0[0], wn[2*j], h4a.x);  fma2(an1[0], wn[2*j+1], h4a.y);
                fma2(ar0[1], wr[2*j], h4b.x);  fma2(ar1[1], wr[2*j+1], h4b.y);
                fma2(az0[1], wz[2*j], h4b.x);  fma2(az1[1], wz[2*j+1], h4b.y);
                fma2(an0[1], wn[2*j], h4b.x);  fma2(an1[1], wn[2*j+1], h4b.y);
            }

            #pragma unroll
            for (int s = 0; s < 2; s++){
                float gr = sigmoidf_(axr[s] + br_ + upk_sum(ar0[s]) + upk_sum(ar1[s]));
                float gz = sigmoidf_(axz[s] + bz_ + upk_sum(az0[s]) + upk_sum(az1[s]));
                float gn = tanhf_(axn[s] + gr*(bn_ + upk_sum(an0[s]) + upk_sum(an1[s])));
                hk[s] = gz*(hk[s] - gn) + gn;
                sh_h[grp][p^1][s][k] = hk[s];
                yout[(size_t)(ob[s] + t)*HH + k] = hk[s];
            }

            asm volatile("bar.sync %0, %1;" :: "r"(grp), "r"(64) : "memory");
            #pragma unroll
            for (int s = 0; s < 2; s++){
                axr[s] = nxr[s]; axz[s] = nxz[s]; axn[s] = nxn[s];
            }
            p ^= 1;
        }
    }

    if (mode == 2 && hid != nullptr){
        #pragma unroll
        for (int s = 0; s < 2; s++){
            int n = n0 + s;
            int bi = n >> 6, sidx = n & 63;
            hid[(size_t)(((bi*4 + layer)*64 + sidx)*64) + k] = hk[s];
        }
    }
}

// ---------- 4) prices passthrough ----------
__global__ void tail_kernel(const float* __restrict__ prices, float* __restrict__ out){
    int i = threadIdx.x;
    if (i < 512) out[i] = prices[i];
}

extern "C" void kernel_launch(void* const* d_in, const int* in_sizes, int n_in,
                              void* d_out, int out_size)
{
    const int*   titles   = (const int*)  d_in[0];
    const int*   contents = (const int*)  d_in[1];
    const float* prices   = (const float*)d_in[2];
    const float* emb      = (const float*)d_in[3];
    const float* iWih0    = (const float*)d_in[4];
    const float* iWhh0    = (const float*)d_in[5];
    const float* ibih0    = (const float*)d_in[6];
    const float* ibhh0    = (const float*)d_in[7];
    const float* iWih     = (const float*)d_in[8];   // [3][192][64]
    const float* iWhh     = (const float*)d_in[9];
    const float* ibih     = (const float*)d_in[10];  // [3][192]
    const float* ibhh     = (const float*)d_in[11];
    const float* cWih     = (const float*)d_in[12];  // [4][192][64]
    const float* cWhh     = (const float*)d_in[13];
    const float* cbih     = (const float*)d_in[14];
    const float* cbhh     = (const float*)d_in[15];

    float* out = (float*)d_out;
    float* hid = out + (size_t)8*64*160*64;          // encoder_hidden region
    float* pr  = hid + (size_t)8*4*64*64;            // prices region

    float *pXG = nullptr, *pA = nullptr, *pB = nullptr;
    cudaGetSymbolAddress((void**)&pXG, g_xg);
    cudaGetSymbolAddress((void**)&pA,  g_A);
    cudaGetSymbolAddress((void**)&pB,  g_B);

    const int GRID_M = (ROWS_ALL/64)*2;   // 2560 (row-tile x col-half)
    const int GRID_R = 128;               // rec: 256 groups x 2 seqs

    // 1) embedding bags
    embed_kernel<<<(ROWS_ALL*75 + 255)/256, 256>>>(titles, contents, emb);

    // info layer 0
    xg_gemm150<<<ROWS_ALL/64, 256>>>(iWih0, ibih0);
    gru_rec64<<<GRID_R, 128>>>(pXG, iWhh0, ibhh0, pA, nullptr, 0, 0);

    // info layers 1..3; layer 3 writes concat layout
    xg_gemm64<<<GRID_M, 256>>>(pA, iWih + 0*GG*HH, ibih + 0*GG);
    gru_rec64<<<GRID_R, 128>>>(pXG, iWhh + 0*GG*HH, ibhh + 0*GG, pB, nullptr, 0, 0);

    xg_gemm64<<<GRID_M, 256>>>(pB, iWih + 1*GG*HH, ibih + 1*GG);
    gru_rec64<<<GRID_R, 128>>>(pXG, iWhh + 1*GG*HH, ibhh + 1*GG, pA, nullptr, 0, 0);

    xg_gemm64<<<GRID_M, 256>>>(pA, iWih + 2*GG*HH, ibih + 2*GG);
    gru_rec64<<<GRID_R, 128>>>(pXG, iWhh + 2*GG*HH, ibhh + 2*GG, pB, nullptr, 1, 0);

    // comb layers 0..3 (concat layout, T=160); final layer writes encoder_outputs
    xg_gemm64<<<GRID_M, 256>>>(pB, cWih + 0*GG*HH, cbih + 0*GG);
    gru_rec64<<<GRID_R, 128>>>(pXG, cWhh + 0*GG*HH, cbhh + 0*GG, pA,  hid, 2, 0);

    xg_gemm64<<<GRID_M, 256>>>(pA, cWih + 1*GG*HH, cbih + 1*GG);
    gru_rec64<<<GRID_R, 128>>>(pXG, cWhh + 1*GG*HH, cbhh + 1*GG, pB,  hid, 2, 1);

    xg_gemm64<<<GRID_M, 256>>>(pB, cWih + 2*GG*HH, cbih + 2*GG);
    gru_rec64<<<GRID_R, 128>>>(pXG, cWhh + 2*GG*HH, cbhh + 2*GG, pA,  hid, 2, 2);

    xg_gemm64<<<GRID_M, 256>>>(pA, cWih + 3*GG*HH, cbih + 3*GG);
    gru_rec64<<<GRID_R, 128>>>(pXG, cWhh + 3*GG*HH, cbhh + 3*GG, out, hid, 2, 3);

    // prices passthrough
    tail_kernel<<<1, 512>>>(prices, pr);
}

// round 16
// speedup vs baseline: 1.0225x; 1.0225x over previous
#include <cuda_runtime.h>
#include <cstdint>

// Problem dims
#define NS   512                 // B*S
#define DD   150
#define HH   64
#define GG   192                 // 3H
#define LTT  32
#define LCC  128
#define LSEQ 160                 // LTT + LCC
#define ROWS_T (NS*LTT)          // 16384
#define ROWS_ALL (NS*(LTT+LCC))  // 81920

// Scratch (device globals; no runtime alloc allowed)
__device__ float g_X [ROWS_ALL*DD];   // embed sums (layer0 input)
__device__ float g_xg[ROWS_ALL*GG];   // per-layer input projection, plain [row][gate]
__device__ float g_A [ROWS_ALL*HH];
__device__ float g_B [ROWS_ALL*HH];

// ---------- f32x2 helpers ----------
__device__ __forceinline__ unsigned long long pk2(float a, float b){
    unsigned long long r; asm("mov.b64 %0,{%1,%2};" : "=l"(r) : "f"(a), "f"(b)); return r;
}
__device__ __forceinline__ void fma2(unsigned long long &acc, unsigned long long a, unsigned long long b){
    asm("fma.rn.f32x2 %0, %1, %2, %0;" : "+l"(acc) : "l"(a), "l"(b));
}
__device__ __forceinline__ float upk_sum(unsigned long long a){
    float x, y; asm("mov.b64 {%0,%1}, %2;" : "=f"(x), "=f"(y) : "l"(a)); return x + y;
}
__device__ __forceinline__ float sigmoidf_(float x){
    return __fdividef(1.f, 1.f + __expf(-x));
}
__device__ __forceinline__ float tanhf_(float x){
    float ax = fabsf(x);
    float e  = __expf(-2.f*ax);
    float t  = __fdividef(1.f - e, 1.f + e);
    return (x < 0.f) ? -t : t;
}

// ---------- 1) embedding-bag sums ----------
__global__ void embed_kernel(const int* __restrict__ titles,
                             const int* __restrict__ contents,
                             const float* __restrict__ emb)
{
    int idx = blockIdx.x*blockDim.x + threadIdx.x;
    if (idx >= ROWS_ALL*75) return;          // 75 float2 per row (D=150)
    int row = idx / 75;
    int dp  = idx - row*75;

    const int* ip; int stride;
    if (row < ROWS_T){ int n = row >> 5, t = row & 31;  ip = titles   + (n*6)*32  + t; stride = 32; }
    else             { int r = row - ROWS_T;
                       int n = r >> 7,   t = r & 127;   ip = contents + (n*6)*128 + t; stride = 128; }

    float ax = 0.f, ay = 0.f;
    #pragma unroll
    for (int i = 0; i < 6; i++){
        int ix = ip[i*stride];
        if (ix != 0){
            float2 v = *(const float2*)(emb + (size_t)ix*DD + 2*dp);
            ax += v.x; ay += v.y;
        }
    }
    *(float2*)(g_X + (size_t)row*DD + 2*dp) = make_float2(ax, ay);
}

// ---------- 2a) layer-0 input projection GEMM (K=150), fp32, plain store ----------
__global__ void __launch_bounds__(256, 3) xg_gemm150(const float* __restrict__ W,
                                                     const float* __restrict__ bias)
{
    __shared__ float  sw [30*194];
    __shared__ float2 sxd[64*31];
    int tid = threadIdx.x;
    int tx = tid & 31, ty = tid >> 5;
    int r0 = blockIdx.x * 64;

    unsigned long long acc[8][3];
    #pragma unroll
    for (int r = 0; r < 8; r++)
        #pragma unroll
        for (int c = 0; c < 3; c++) acc[r][c] = 0ull;

    for (int k0 = 0; k0 < 150; k0 += 30){
        for (int i = tid; i < 30*192; i += 256){
            int gg = i/30, kk = i - gg*30;
            sw[kk*194 + gg] = W[gg*150 + k0 + kk];
        }
        for (int i = tid; i < 64*30; i += 256){
            int rr = i/30, kk = i - rr*30;
            float v = g_X[(size_t)(r0+rr)*150 + k0 + kk];
            sxd[rr*31 + kk] = make_float2(v, v);
        }
        __syncthreads();
        #pragma unroll 6
        for (int kk = 0; kk < 30; kk++){
            unsigned long long w2[3];
            #pragma unroll
            for (int c = 0; c < 3; c++)
                w2[c] = *(const unsigned long long*)&sw[kk*194 + tx*6 + 2*c];
            #pragma unroll
            for (int r = 0; r < 8; r++){
                unsigned long long x2 = *(const unsigned long long*)&sxd[(ty*8 + r)*31 + kk];
                #pragma unroll
                for (int c = 0; c < 3; c++) fma2(acc[r][c], w2[c], x2);
            }
        }
        __syncthreads();
    }
    #pragma unroll
    for (int r = 0; r < 8; r++){
        int row = r0 + ty*8 + r;
        #pragma unroll
        for (int c = 0; c < 3; c++){
            float lo, hi;
            asm("mov.b64 {%0,%1}, %2;" : "=f"(lo), "=f"(hi) : "l"(acc[r][c]));
            int g0 = tx*6 + 2*c;
            float2 o; o.x = lo + bias[g0]; o.y = hi + bias[g0+1];
            *(float2*)(g_xg + (size_t)row*GG + g0) = o;
        }
    }
}

// ---------- 2b) K=64 projection GEMM, k-paired f32x2, no duplication ----------
// Tile 64 rows x 96 cols (half of GG). Grid = (ROWS_ALL/64)*2.
// Single smem fill (full K=64), ONE barrier, 16 fully-unrolled 4-k blocks.
#define SWP 68   // padded row stride (floats): 272B, 16B-aligned
__global__ void __launch_bounds__(256, 3) xg_gemm64(const float* __restrict__ X,
                                                    const float* __restrict__ W,
                                                    const float* __restrict__ bias)
{
    __shared__ float sw[96*SWP];
    __shared__ float sx[64*SWP];
    const int tid = threadIdx.x;
    const int tx = tid & 31, ty = tid >> 5;
    const int r0 = (blockIdx.x >> 1) * 64;
    const int c0 = (blockIdx.x & 1) * 96;

    for (int i = tid; i < 96*16; i += 256){
        int g = i >> 4, kq = i & 15;
        float4 v = *(const float4*)(W + (size_t)(c0 + g)*64 + kq*4);
        *(float4*)(sw + g*SWP + kq*4) = v;
    }
    for (int i = tid; i < 64*16; i += 256){
        int r = i >> 4, kq = i & 15;
        float4 v = *(const float4*)(X + (size_t)(r0 + r)*64 + kq*4);
        *(float4*)(sx + r*SWP + kq*4) = v;
    }
    __syncthreads();

    unsigned long long acc[8][3];
    #pragma unroll
    for (int r = 0; r < 8; r++)
        #pragma unroll
        for (int c = 0; c < 3; c++) acc[r][c] = 0ull;

    #pragma unroll
    for (int k4 = 0; k4 < 16; k4++){
        ulonglong2 wv[3];
        #pragma unroll
        for (int c = 0; c < 3; c++)
            wv[c] = *(const ulonglong2*)(sw + (tx + 32*c)*SWP + k4*4);
        #pragma unroll
        for (int r = 0; r < 8; r++){
            ulonglong2 xv = *(const ulonglong2*)(sx + (ty*8 + r)*SWP + k4*4);
            #pragma unroll
            for (int c = 0; c < 3; c++){
                fma2(acc[r][c], wv[c].x, xv.x);
                fma2(acc[r][c], wv[c].y, xv.y);
            }
        }
    }

    #pragma unroll
    for (int r = 0; r < 8; r++){
        int row = r0 + ty*8 + r;
        #pragma unroll
        for (int c = 0; c < 3; c++){
            int col = c0 + tx + 32*c;
            g_xg[(size_t)row*GG + col] = upk_sum(acc[r][c]) + __ldg(bias + col);
        }
    }
}

// ---------- 3) GRU recurrence: 64-thread groups, 2 seqs/group, 6 acc chains ----------
// Block 128 = 2 groups of 64 threads; grid 128 (256 groups x 2 seqs = 512 seqs;
// 2 CTAs/SM). Thread k owns gate rows k (r), 64+k (z), 128+k (n) and advances
// BOTH sequences each step. SIX depth-32 accumulator chains (1 per gate-seq)
// keep register count ~237 < 255 (the R14 12-chain version spilled).
// One named barrier (id=grp, 64 thr) per step; h double-buffered in shared.
// mode 0: info mid (X layout out), mode 1: info final (concat out), mode 2: comb.
__global__ void __launch_bounds__(128, 2) gru_rec64(
    const float* __restrict__ xg,
    const float* __restrict__ Whh, const float* __restrict__ bhh,
    float* __restrict__ yout, float* __restrict__ hid,
    int mode, int layer)
{
    __shared__ __align__(16) float sh_h[2][2][2][64];   // [grp][buf][seq][elem]

    const int tid = threadIdx.x;
    const int grp = tid >> 6, k = tid & 63;
    const int n0 = (blockIdx.x*2 + grp)*2;    // first seq id of this group (0..510)

    // weight rows r,z,n -> registers (3 x 32 f32x2)
    unsigned long long wr[32], wz[32], wn[32];
    {
        const float2* pr_ = (const float2*)(Whh + (size_t)k*HH);
        const float2* pz_ = (const float2*)(Whh + (size_t)(64 + k)*HH);
        const float2* pn_ = (const float2*)(Whh + (size_t)(128 + k)*HH);
        #pragma unroll
        for (int j = 0; j < 32; j++){
            float2 a = __ldg(pr_ + j); wr[j] = pk2(a.x, a.y);
            float2 b = __ldg(pz_ + j); wz[j] = pk2(b.x, b.y);
            float2 c = __ldg(pn_ + j); wn[j] = pk2(c.x, c.y);
        }
    }
    const float br_ = bhh[k], bz_ = bhh[64 + k], bn_ = bhh[128 + k];

    const int NSEG = (mode == 2) ? 1 : 2;
    float hk[2] = {0.f, 0.f};

    for (int seg = 0; seg < NSEG; seg++){
        int T, ibase[2], ob[2];
        if (mode == 2){
            T = LSEQ;
            #pragma unroll
            for (int s = 0; s < 2; s++){ ibase[s] = (n0+s)*LSEQ; ob[s] = ibase[s]; }
        } else if (seg == 0){   // content
            T = LCC;
            #pragma unroll
            for (int s = 0; s < 2; s++){
                ibase[s] = ROWS_T + (n0+s)*LCC;
                ob[s] = (mode == 1) ? (n0+s)*LSEQ + LTT : ibase[s];
            }
        } else {                // titles
            T = LTT;
            #pragma unroll
            for (int s = 0; s < 2; s++){
                ibase[s] = (n0+s)*LTT;
                ob[s] = (mode == 1) ? (n0+s)*LSEQ : ibase[s];
            }
        }

        hk[0] = hk[1] = 0.f;
        sh_h[grp][0][0][k] = 0.f;
        sh_h[grp][0][1][k] = 0.f;

        float axr[2], axz[2], axn[2];
        #pragma unroll
        for (int s = 0; s < 2; s++){
            int xo = ibase[s]*GG + k;
            axr[s] = __ldg(xg + xo);
            axz[s] = __ldg(xg + xo + 64);
            axn[s] = __ldg(xg + xo + 128);
        }
        asm volatile("bar.sync %0, %1;" :: "r"(grp), "r"(64) : "memory");

        int p = 0;
        for (int t = 0; t < T; t++){
            // prefetch next step's xg (both seqs)
            float nxr[2], nxz[2], nxn[2];
            #pragma unroll
            for (int s = 0; s < 2; s++){
                nxr[s] = nxz[s] = nxn[s] = 0.f;
                if (t+1 < T){
                    int xo = (ibase[s] + t + 1)*GG + k;
                    nxr[s] = __ldg(xg + xo);
                    nxz[s] = __ldg(xg + xo + 64);
                    nxn[s] = __ldg(xg + xo + 128);
                }
            }

            // six matvecs (3 gates x 2 seqs), ONE depth-32 chain each
            unsigned long long ar[2], az[2], an[2];
            ar[0]=ar[1]=az[0]=az[1]=an[0]=an[1]=0ull;
            const ulonglong2* hp0 = (const ulonglong2*)sh_h[grp][p][0];
            const ulonglong2* hp1 = (const ulonglong2*)sh_h[grp][p][1];
            #pragma unroll
            for (int j = 0; j < 16; j++){
                ulonglong2 h4a = hp0[j];
                ulonglong2 h4b = hp1[j];
                fma2(ar[0], wr[2*j], h4a.x);  fma2(ar[0], wr[2*j+1], h4a.y);
                fma2(az[0], wz[2*j], h4a.x);  fma2(az[0], wz[2*j+1], h4a.y);
                fma2(an[0], wn[2*j], h4a.x);  fma2(an[0], wn[2*j+1], h4a.y);
                fma2(ar[1], wr[2*j], h4b.x);  fma2(ar[1], wr[2*j+1], h4b.y);
                fma2(az[1], wz[2*j], h4b.x);  fma2(az[1], wz[2*j+1], h4b.y);
                fma2(an[1], wn[2*j], h4b.x);  fma2(an[1], wn[2*j+1], h4b.y);
            }

            #pragma unroll
            for (int s = 0; s < 2; s++){
                float gr = sigmoidf_(axr[s] + br_ + upk_sum(ar[s]));
                float gz = sigmoidf_(axz[s] + bz_ + upk_sum(az[s]));
                float gn = tanhf_(axn[s] + gr*(bn_ + upk_sum(an[s])));
                hk[s] = gz*(hk[s] - gn) + gn;
                sh_h[grp][p^1][s][k] = hk[s];
                yout[(size_t)(ob[s] + t)*HH + k] = hk[s];
            }

            asm volatile("bar.sync %0, %1;" :: "r"(grp), "r"(64) : "memory");
            #pragma unroll
            for (int s = 0; s < 2; s++){
                axr[s] = nxr[s]; axz[s] = nxz[s]; axn[s] = nxn[s];
            }
            p ^= 1;
        }
    }

    if (mode == 2 && hid != nullptr){
        #pragma unroll
        for (int s = 0; s < 2; s++){
            int n = n0 + s;
            int bi = n >> 6, sidx = n & 63;
            hid[(size_t)(((bi*4 + layer)*64 + sidx)*64) + k] = hk[s];
        }
    }
}

// ---------- 4) prices passthrough ----------
__global__ void tail_kernel(const float* __restrict__ prices, float* __restrict__ out){
    int i = threadIdx.x;
    if (i < 512) out[i] = prices[i];
}

extern "C" void kernel_launch(void* const* d_in, const int* in_sizes, int n_in,
                              void* d_out, int out_size)
{
    const int*   titles   = (const int*)  d_in[0];
    const int*   contents = (const int*)  d_in[1];
    const float* prices   = (const float*)d_in[2];
    const float* emb      = (const float*)d_in[3];
    const float* iWih0    = (const float*)d_in[4];
    const float* iWhh0    = (const float*)d_in[5];
    const float* ibih0    = (const float*)d_in[6];
    const float* ibhh0    = (const float*)d_in[7];
    const float* iWih     = (const float*)d_in[8];   // [3][192][64]
    const float* iWhh     = (const float*)d_in[9];
    const float* ibih     = (const float*)d_in[10];  // [3][192]
    const float* ibhh     = (const float*)d_in[11];
    const float* cWih     = (const float*)d_in[12];  // [4][192][64]
    const float* cWhh     = (const float*)d_in[13];
    const float* cbih     = (const float*)d_in[14];
    const float* cbhh     = (const float*)d_in[15];

    float* out = (float*)d_out;
    float* hid = out + (size_t)8*64*160*64;          // encoder_hidden region
    float* pr  = hid + (size_t)8*4*64*64;            // prices region

    float *pXG = nullptr, *pA = nullptr, *pB = nullptr;
    cudaGetSymbolAddress((void**)&pXG, g_xg);
    cudaGetSymbolAddress((void**)&pA,  g_A);
    cudaGetSymbolAddress((void**)&pB,  g_B);

    const int GRID_M = (ROWS_ALL/64)*2;   // 2560 (row-tile x col-half)
    const int GRID_R = 128;               // rec: 256 groups x 2 seqs

    // 1) embedding bags
    embed_kernel<<<(ROWS_ALL*75 + 255)/256, 256>>>(titles, contents, emb);

    // info layer 0
    xg_gemm150<<<ROWS_ALL/64, 256>>>(iWih0, ibih0);
    gru_rec64<<<GRID_R, 128>>>(pXG, iWhh0, ibhh0, pA, nullptr, 0, 0);

    // info layers 1..3; layer 3 writes concat layout
    xg_gemm64<<<GRID_M, 256>>>(pA, iWih + 0*GG*HH, ibih + 0*GG);
    gru_rec64<<<GRID_R, 128>>>(pXG, iWhh + 0*GG*HH, ibhh + 0*GG, pB, nullptr, 0, 0);

    xg_gemm64<<<GRID_M, 256>>>(pB, iWih + 1*GG*HH, ibih + 1*GG);
    gru_rec64<<<GRID_R, 128>>>(pXG, iWhh + 1*GG*HH, ibhh + 1*GG, pA, nullptr, 0, 0);

    xg_gemm64<<<GRID_M, 256>>>(pA, iWih + 2*GG*HH, ibih + 2*GG);
    gru_rec64<<<GRID_R, 128>>>(pXG, iWhh + 2*GG*HH, ibhh + 2*GG, pB, nullptr, 1, 0);

    // comb layers 0..3 (concat layout, T=160); final layer writes encoder_outputs
    xg_gemm64<<<GRID_M, 256>>>(pB, cWih + 0*GG*HH, cbih + 0*GG);
    gru_rec64<<<GRID_R, 128>>>(pXG, cWhh + 0*GG*HH, cbhh + 0*GG, pA,  hid, 2, 0);

    xg_gemm64<<<GRID_M, 256>>>(pA, cWih + 1*GG*HH, cbih + 1*GG);
    gru_rec64<<<GRID_R, 128>>>(pXG, cWhh + 1*GG*HH, cbhh + 1*GG, pB,  hid, 2, 1);

    xg_gemm64<<<GRID_M, 256>>>(pB, cWih + 2*GG*HH, cbih + 2*GG);
    gru_rec64<<<GRID_R, 128>>>(pXG, cWhh + 2*GG*HH, cbhh + 2*GG, pA,  hid, 2, 2);

    xg_gemm64<<<GRID_M, 256>>>(pA, cWih + 3*GG*HH, cbih + 3*GG);
    gru_rec64<<<GRID_R, 128>>>(pXG, cWhh + 3*GG*HH, cbhh + 3*GG, out, hid, 2, 3);

    // prices passthrough
    tail_kernel<<<1, 512>>>(prices, pr);
}

// round 17
// speedup vs baseline: 1.3026x; 1.2739x over previous
#include <cuda_runtime.h>
#include <cstdint>

// Problem dims
#define NS   512                 // B*S
#define DD   150
#define HH   64
#define GG   192                 // 3H
#define VV   30522               // vocab
#define LTT  32
#define LCC  128
#define LSEQ 160                 // LTT + LCC
#define ROWS_T (NS*LTT)          // 16384
#define ROWS_ALL (NS*(LTT+LCC))  // 81920

// Scratch (device globals; no runtime alloc allowed)
__device__ float g_EP [VV*GG];        // projected embedding table (emb @ Wih0^T)
__device__ float g_xg[ROWS_ALL*GG];   // per-layer input projection, plain [row][gate]
__device__ float g_A [ROWS_ALL*HH];
__device__ float g_B [ROWS_ALL*HH];

// ---------- f32x2 helpers ----------
__device__ __forceinline__ unsigned long long pk2(float a, float b){
    unsigned long long r; asm("mov.b64 %0,{%1,%2};" : "=l"(r) : "f"(a), "f"(b)); return r;
}
__device__ __forceinline__ void fma2(unsigned long long &acc, unsigned long long a, unsigned long long b){
    asm("fma.rn.f32x2 %0, %1, %2, %0;" : "+l"(acc) : "l"(a), "l"(b));
}
__device__ __forceinline__ float upk_sum(unsigned long long a){
    float x, y; asm("mov.b64 {%0,%1}, %2;" : "=f"(x), "=f"(y) : "l"(a)); return x + y;
}
__device__ __forceinline__ float sigmoidf_(float x){
    return __fdividef(1.f, 1.f + __expf(-x));
}
__device__ __forceinline__ float tanhf_(float x){
    float ax = fabsf(x);
    float e  = __expf(-2.f*ax);
    float t  = __fdividef(1.f - e, 1.f + e);
    return (x < 0.f) ? -t : t;
}

// ---------- 1) embedding-table projection GEMM: g_EP = emb @ Wih0^T ----------
// 30522x192x150 (1.76 GFLOP vs 4.7 GFLOP for projecting gathered rows).
// Tile 64 vocab-rows x 96 gates; K padded 150->160, 4 chunks of 40, k-paired f32x2.
#define SP2 44   // padded chunk row stride (floats): 176B, 16B-aligned
__global__ void __launch_bounds__(256, 3) proj_gemm(const float* __restrict__ emb,
                                                    const float* __restrict__ W)
{
    __shared__ float sw[96*SP2];
    __shared__ float sx[64*SP2];
    const int tid = threadIdx.x;
    const int tx = tid & 31, ty = tid >> 5;
    const int r0 = (blockIdx.x >> 1) * 64;
    const int c0 = (blockIdx.x & 1) * 96;

    unsigned long long acc[8][3];
    #pragma unroll
    for (int r = 0; r < 8; r++)
        #pragma unroll
        for (int c = 0; c < 3; c++) acc[r][c] = 0ull;

    for (int kc = 0; kc < 4; kc++){
        const int k0 = kc*40;
        for (int i = tid; i < 96*40; i += 256){
            int g = i/40, kk = i - g*40, k = k0 + kk;
            sw[g*SP2 + kk] = (k < DD) ? W[(size_t)(c0 + g)*DD + k] : 0.f;
        }
        for (int i = tid; i < 64*40; i += 256){
            int r = i/40, kk = i - r*40, k = k0 + kk;
            int row = r0 + r;
            sx[r*SP2 + kk] = (row < VV && k < DD) ? emb[(size_t)row*DD + k] : 0.f;
        }
        __syncthreads();
        #pragma unroll
        for (int k4 = 0; k4 < 10; k4++){
            ulonglong2 wv[3];
            #pragma unroll
            for (int c = 0; c < 3; c++)
                wv[c] = *(const ulonglong2*)(sw + (tx + 32*c)*SP2 + k4*4);
            #pragma unroll
            for (int r = 0; r < 8; r++){
                ulonglong2 xv = *(const ulonglong2*)(sx + (ty*8 + r)*SP2 + k4*4);
                #pragma unroll
                for (int c = 0; c < 3; c++){
                    fma2(acc[r][c], wv[c].x, xv.x);
                    fma2(acc[r][c], wv[c].y, xv.y);
                }
            }
        }
        __syncthreads();
    }
    #pragma unroll
    for (int r = 0; r < 8; r++){
        int row = r0 + ty*8 + r;
        if (row < VV){
            #pragma unroll
            for (int c = 0; c < 3; c++){
                int col = c0 + tx + 32*c;
                g_EP[(size_t)row*GG + col] = upk_sum(acc[r][c]);
            }
        }
    }
}

// ---------- 2) embedding-bag in projected (192-d) space + bias ----------
// xg[row][:] = bih + sum_i g_EP[idx_i][:]; one thread per (row, float4 chunk).
__global__ void bag_kernel(const int* __restrict__ titles,
                           const int* __restrict__ contents,
                           const float* __restrict__ bias)
{
    int idx = blockIdx.x*blockDim.x + threadIdx.x;
    if (idx >= ROWS_ALL*48) return;          // 48 float4 per row (GG=192)
    int row = idx / 48;
    int q   = idx - row*48;

    const int* ip; int stride;
    if (row < ROWS_T){ int n = row >> 5, t = row & 31;  ip = titles   + (n*6)*32  + t; stride = 32; }
    else             { int r = row - ROWS_T;
                       int n = r >> 7,   t = r & 127;   ip = contents + (n*6)*128 + t; stride = 128; }

    float4 a = ((const float4*)bias)[q];
    #pragma unroll
    for (int i = 0; i < 6; i++){
        int ix = ip[i*stride];
        if (ix != 0){
            float4 v = *(const float4*)(g_EP + (size_t)ix*GG + 4*q);
            a.x += v.x; a.y += v.y; a.z += v.z; a.w += v.w;
        }
    }
    *(float4*)(g_xg + (size_t)row*GG + 4*q) = a;
}

// ---------- 3) K=64 projection GEMM, k-paired f32x2 (layers 1+) ----------
// Tile 64 rows x 96 cols (half of GG). Grid = (ROWS_ALL/64)*2.
// Single smem fill (full K=64), ONE barrier, 16 fully-unrolled 4-k blocks.
#define SWP 68   // padded row stride (floats): 272B, 16B-aligned
__global__ void __launch_bounds__(256, 3) xg_gemm64(const float* __restrict__ X,
                                                    const float* __restrict__ W,
                                                    const float* __restrict__ bias)
{
    __shared__ float sw[96*SWP];
    __shared__ float sx[64*SWP];
    const int tid = threadIdx.x;
    const int tx = tid & 31, ty = tid >> 5;
    const int r0 = (blockIdx.x >> 1) * 64;
    const int c0 = (blockIdx.x & 1) * 96;

    for (int i = tid; i < 96*16; i += 256){
        int g = i >> 4, kq = i & 15;
        float4 v = *(const float4*)(W + (size_t)(c0 + g)*64 + kq*4);
        *(float4*)(sw + g*SWP + kq*4) = v;
    }
    for (int i = tid; i < 64*16; i += 256){
        int r = i >> 4, kq = i & 15;
        float4 v = *(const float4*)(X + (size_t)(r0 + r)*64 + kq*4);
        *(float4*)(sx + r*SWP + kq*4) = v;
    }
    __syncthreads();

    unsigned long long acc[8][3];
    #pragma unroll
    for (int r = 0; r < 8; r++)
        #pragma unroll
        for (int c = 0; c < 3; c++) acc[r][c] = 0ull;

    #pragma unroll
    for (int k4 = 0; k4 < 16; k4++){
        ulonglong2 wv[3];
        #pragma unroll
        for (int c = 0; c < 3; c++)
            wv[c] = *(const ulonglong2*)(sw + (tx + 32*c)*SWP + k4*4);
        #pragma unroll
        for (int r = 0; r < 8; r++){
            ulonglong2 xv = *(const ulonglong2*)(sx + (ty*8 + r)*SWP + k4*4);
            #pragma unroll
            for (int c = 0; c < 3; c++){
                fma2(acc[r][c], wv[c].x, xv.x);
                fma2(acc[r][c], wv[c].y, xv.y);
            }
        }
    }

    #pragma unroll
    for (int r = 0; r < 8; r++){
        int row = r0 + ty*8 + r;
        #pragma unroll
        for (int c = 0; c < 3; c++){
            int col = c0 + tx + 32*c;
            g_xg[(size_t)row*GG + col] = upk_sum(acc[r][c]) + __ldg(bias + col);
        }
    }
}

// ---------- 4) GRU recurrence (R13-proven): 64-thread groups, 1 seq/group ----------
// Block 128 = 2 groups of 64 threads; grid 256 (512 seqs; 2 CTAs/SM).
// Thread k owns gate rows k (r), 64+k (z), 128+k (n): all gates + h-update
// computed locally. One named barrier (id=grp, 64 thr) per step; h double-
// buffered in shared. Accumulators split into 2 chains each (depth 16).
// mode 0: info mid (X layout out), mode 1: info final (concat out), mode 2: comb.
__global__ void __launch_bounds__(128, 2) gru_rec64(
    const float* __restrict__ xg,
    const float* __restrict__ Whh, const float* __restrict__ bhh,
    float* __restrict__ yout, float* __restrict__ hid,
    int mode, int layer)
{
    __shared__ __align__(16) float sh_h[2][2][64];

    const int tid = threadIdx.x;
    const int grp = tid >> 6, k = tid & 63;
    const int gid = blockIdx.x*2 + grp;        // 0..511

    // weight rows r,z,n -> registers (3 x 32 f32x2)
    unsigned long long wr[32], wz[32], wn[32];
    {
        const float2* pr_ = (const float2*)(Whh + (size_t)k*HH);
        const float2* pz_ = (const float2*)(Whh + (size_t)(64 + k)*HH);
        const float2* pn_ = (const float2*)(Whh + (size_t)(128 + k)*HH);
        #pragma unroll
        for (int j = 0; j < 32; j++){
            float2 a = __ldg(pr_ + j); wr[j] = pk2(a.x, a.y);
            float2 b = __ldg(pz_ + j); wz[j] = pk2(b.x, b.y);
            float2 c = __ldg(pn_ + j); wn[j] = pk2(c.x, c.y);
        }
    }
    const float br_ = bhh[k], bz_ = bhh[64 + k], bn_ = bhh[128 + k];

    const int NSEG = (mode == 2) ? 1 : 2;
    float hk = 0.f;

    for (int seg = 0; seg < NSEG; seg++){
        int T, ibase, ob;
        if (mode == 2){        ibase = gid*LSEQ;            T = LSEQ; ob = ibase; }
        else if (seg == 0){    ibase = ROWS_T + gid*LCC;    T = LCC;
                               ob = (mode == 1) ? gid*LSEQ + LTT : ibase; }
        else {                 ibase = gid*LTT;             T = LTT;
                               ob = (mode == 1) ? gid*LSEQ : ibase; }

        hk = 0.f;
        sh_h[grp][0][k] = 0.f;

        int xoff = ibase*GG + k;
        float axr = __ldg(xg + xoff);
        float axz = __ldg(xg + xoff + 64);
        float axn = __ldg(xg + xoff + 128);
        asm volatile("bar.sync %0, %1;" :: "r"(grp), "r"(64) : "memory");

        int p = 0;
        for (int t = 0; t < T; t++){
            // prefetch next step's xg
            float nxr = 0.f, nxz = 0.f, nxn = 0.f;
            if (t+1 < T){
                int xo = (ibase + t + 1)*GG + k;
                nxr = __ldg(xg + xo);
                nxz = __ldg(xg + xo + 64);
                nxn = __ldg(xg + xo + 128);
            }

            // three matvecs, 2 chains each (depth 16)
            unsigned long long ar0 = 0ull, ar1 = 0ull;
            unsigned long long az0 = 0ull, az1 = 0ull;
            unsigned long long an0 = 0ull, an1 = 0ull;
            const ulonglong2* hp = (const ulonglong2*)sh_h[grp][p];
            #pragma unroll
            for (int j = 0; j < 16; j++){
                ulonglong2 h4 = hp[j];
                fma2(ar0, wr[2*j],   h4.x);  fma2(ar1, wr[2*j+1], h4.y);
                fma2(az0, wz[2*j],   h4.x);  fma2(az1, wz[2*j+1], h4.y);
                fma2(an0, wn[2*j],   h4.x);  fma2(an1, wn[2*j+1], h4.y);
            }

            float gr = sigmoidf_(axr + br_ + upk_sum(ar0) + upk_sum(ar1));
            float gz = sigmoidf_(axz + bz_ + upk_sum(az0) + upk_sum(az1));
            float gn = tanhf_(axn + gr*(bn_ + upk_sum(an0) + upk_sum(an1)));
            hk = gz*(hk - gn) + gn;

            sh_h[grp][p^1][k] = hk;
            yout[(size_t)(ob + t)*HH + k] = hk;

            asm volatile("bar.sync %0, %1;" :: "r"(grp), "r"(64) : "memory");
            axr = nxr; axz = nxz; axn = nxn;
            p ^= 1;
        }
    }

    if (mode == 2 && hid != nullptr){
        int bi = gid >> 6, sidx = gid & 63;
        hid[(size_t)(((bi*4 + layer)*64 + sidx)*64) + k] = hk;
    }
}

// ---------- 5) prices passthrough ----------
__global__ void tail_kernel(const float* __restrict__ prices, float* __restrict__ out){
    int i = threadIdx.x;
    if (i < 512) out[i] = prices[i];
}

extern "C" void kernel_launch(void* const* d_in, const int* in_sizes, int n_in,
                              void* d_out, int out_size)
{
    const int*   titles   = (const int*)  d_in[0];
    const int*   contents = (const int*)  d_in[1];
    const float* prices   = (const float*)d_in[2];
    const float* emb      = (const float*)d_in[3];
    const float* iWih0    = (const float*)d_in[4];
    const float* iWhh0    = (const float*)d_in[5];
    const float* ibih0    = (const float*)d_in[6];
    const float* ibhh0    = (const float*)d_in[7];
    const float* iWih     = (const float*)d_in[8];   // [3][192][64]
    const float* iWhh     = (const float*)d_in[9];
    const float* ibih     = (const float*)d_in[10];  // [3][192]
    const float* ibhh     = (const float*)d_in[11];
    const float* cWih     = (const float*)d_in[12];  // [4][192][64]
    const float* cWhh     = (const float*)d_in[13];
    const float* cbih     = (const float*)d_in[14];
    const float* cbhh     = (const float*)d_in[15];

    float* out = (float*)d_out;
    float* hid = out + (size_t)8*64*160*64;          // encoder_hidden region
    float* pr  = hid + (size_t)8*4*64*64;            // prices region

    float *pXG = nullptr, *pA = nullptr, *pB = nullptr;
    cudaGetSymbolAddress((void**)&pXG, g_xg);
    cudaGetSymbolAddress((void**)&pA,  g_A);
    cudaGetSymbolAddress((void**)&pB,  g_B);

    const int GRID_M = (ROWS_ALL/64)*2;       // 2560 (row-tile x col-half)
    const int GRID_P = ((VV + 63)/64)*2;      // 954  (proj GEMM)
    const int GRID_R = 256;                   // rec: 512 groups / 2 per CTA

    // layer-0 path: project the embedding TABLE, then bag in 192-d (+bias)
    proj_gemm<<<GRID_P, 256>>>(emb, iWih0);
    bag_kernel<<<(ROWS_ALL*48 + 255)/256, 256>>>(titles, contents, ibih0);
    gru_rec64<<<GRID_R, 128>>>(pXG, iWhh0, ibhh0, pA, nullptr, 0, 0);

    // info layers 1..3; layer 3 writes concat layout
    xg_gemm64<<<GRID_M, 256>>>(pA, iWih + 0*GG*HH, ibih + 0*GG);
    gru_rec64<<<GRID_R, 128>>>(pXG, iWhh + 0*GG*HH, ibhh + 0*GG, pB, nullptr, 0, 0);

    xg_gemm64<<<GRID_M, 256>>>(pB, iWih + 1*GG*HH, ibih + 1*GG);
    gru_rec64<<<GRID_R, 128>>>(pXG, iWhh + 1*GG*HH, ibhh + 1*GG, pA, nullptr, 0, 0);

    xg_gemm64<<<GRID_M, 256>>>(pA, iWih + 2*GG*HH, ibih + 2*GG);
    gru_rec64<<<GRID_R, 128>>>(pXG, iWhh + 2*GG*HH, ibhh + 2*GG, pB, nullptr, 1, 0);

    // comb layers 0..3 (concat layout, T=160); final layer writes encoder_outputs
    xg_gemm64<<<GRID_M, 256>>>(pB, cWih + 0*GG*HH, cbih + 0*GG);
    gru_rec64<<<GRID_R, 128>>>(pXG, cWhh + 0*GG*HH, cbhh + 0*GG, pA,  hid, 2, 0);

    xg_gemm64<<<GRID_M, 256>>>(pA, cWih + 1*GG*HH, cbih + 1*GG);
    gru_rec64<<<GRID_R, 128>>>(pXG, cWhh + 1*GG*HH, cbhh + 1*GG, pB,  hid, 2, 1);

    xg_gemm64<<<GRID_M, 256>>>(pB, cWih + 2*GG*HH, cbih + 2*GG);
    gru_rec64<<<GRID_R, 128>>>(pXG, cWhh + 2*GG*HH, cbhh + 2*GG, pA,  hid, 2, 2);

    xg_gemm64<<<GRID_M, 256>>>(pA, cWih + 3*GG*HH, cbih + 3*GG);
    gru_rec64<<<GRID_R, 128>>>(pXG, cWhh + 3*GG*HH, cbhh + 3*GG, out, hid, 2, 3);

    // prices passthrough
    tail_kernel<<<1, 512>>>(prices, pr);
}